// round 2
// baseline (speedup 1.0000x reference)
#include <cuda_runtime.h>
#include <cuda_bf16.h>

// ---------------------------------------------------------------------------
// HyperbolicGraphPooling: out[g] = sum_{n: batch[n]==g} sigmoid(f[n]·W+b) * f[n]
// N=500000 nodes, C=256 channels, 2048 graphs, batch sorted ascending.
// batch is int32 on device (JAX x64-disabled downcasts jnp.int64 -> int32).
// Strategy: warp-per-node-range, register accumulators, atomic flush on
// segment change. HBM-read-bound (~512 MB), target ~90-140 us.
// ---------------------------------------------------------------------------

#define CHANNELS 256
#define THREADS  256

__global__ void hgp_zero_kernel(float4* __restrict__ out, int n4) {
    int i = blockIdx.x * blockDim.x + threadIdx.x;
    if (i < n4) out[i] = make_float4(0.f, 0.f, 0.f, 0.f);
}

__device__ __forceinline__ void flush_seg(float* __restrict__ out,
                                          int seg, int num_segs, int lane,
                                          const float4& a0, const float4& a1) {
    if (seg < 0 || seg >= num_segs) return;   // defensive; ~2 execs per warp
    float* p0 = out + (size_t)seg * CHANNELS + 4 * lane;
    float* p1 = p0 + 128;
    atomicAdd(p0 + 0, a0.x);
    atomicAdd(p0 + 1, a0.y);
    atomicAdd(p0 + 2, a0.z);
    atomicAdd(p0 + 3, a0.w);
    atomicAdd(p1 + 0, a1.x);
    atomicAdd(p1 + 1, a1.y);
    atomicAdd(p1 + 2, a1.z);
    atomicAdd(p1 + 3, a1.w);
}

__global__ __launch_bounds__(THREADS)
void hgp_pool_kernel(const float* __restrict__ feat,
                     const int* __restrict__ batch,
                     const float* __restrict__ W,
                     const float* __restrict__ b,
                     float* __restrict__ out,
                     int N, int num_segs) {
    const int lane        = threadIdx.x & 31;
    const int warp_global = (blockIdx.x * blockDim.x + threadIdx.x) >> 5;
    const int total_warps = (gridDim.x * blockDim.x) >> 5;

    // Contiguous node range for this warp
    const int per = (N + total_warps - 1) / total_warps;
    const int n0  = warp_global * per;
    const int n1  = (n0 + per < N) ? (n0 + per) : N;
    if (n0 >= n1) return;

    // Per-lane attention weights (channels [4*lane,4*lane+4) and +128)
    const float4 w0 = *reinterpret_cast<const float4*>(W + 4 * lane);
    const float4 w1 = *reinterpret_cast<const float4*>(W + 128 + 4 * lane);
    const float bias = b[0];

    float4 a0 = make_float4(0.f, 0.f, 0.f, 0.f);
    float4 a1 = make_float4(0.f, 0.f, 0.f, 0.f);
    int cur = batch[n0];

    // Prime pipeline: load row n0
    const float4* row = reinterpret_cast<const float4*>(feat + (size_t)n0 * CHANNELS);
    float4 f0 = row[lane];
    float4 f1 = row[32 + lane];
    int g = cur;

    for (int n = n0; n < n1; ++n) {
        // Prefetch next iteration's row + batch id before the dependent chain
        float4 nf0, nf1;
        int ng = 0;
        const int np = n + 1;
        if (np < n1) {
            const float4* nrow =
                reinterpret_cast<const float4*>(feat + (size_t)np * CHANNELS);
            nf0 = nrow[lane];
            nf1 = nrow[32 + lane];
            ng  = batch[np];
        }

        // Segment boundary: flush register accumulator
        if (g != cur) {
            flush_seg(out, cur, num_segs, lane, a0, a1);
            a0 = make_float4(0.f, 0.f, 0.f, 0.f);
            a1 = make_float4(0.f, 0.f, 0.f, 0.f);
            cur = g;
        }

        // Per-lane partial dot (8 channels)
        float s = f0.x * w0.x + f0.y * w0.y + f0.z * w0.z + f0.w * w0.w
                + f1.x * w1.x + f1.y * w1.y + f1.z * w1.z + f1.w * w1.w;
        // Full warp reduce (all lanes get the sum)
        #pragma unroll
        for (int o = 16; o > 0; o >>= 1)
            s += __shfl_xor_sync(0xFFFFFFFFu, s, o);

        const float wgt = 1.0f / (1.0f + __expf(-(s + bias)));

        a0.x += f0.x * wgt; a0.y += f0.y * wgt;
        a0.z += f0.z * wgt; a0.w += f0.w * wgt;
        a1.x += f1.x * wgt; a1.y += f1.y * wgt;
        a1.z += f1.z * wgt; a1.w += f1.w * wgt;

        f0 = nf0; f1 = nf1; g = ng;
    }

    flush_seg(out, cur, num_segs, lane, a0, a1);
}

extern "C" void kernel_launch(void* const* d_in, const int* in_sizes, int n_in,
                              void* d_out, int out_size) {
    const float* feat  = (const float*)d_in[0];  // [N, 256] f32
    const int*   batch = (const int*)d_in[1];    // [N] i32, sorted
    const float* W     = (const float*)d_in[2];  // [256, 1] f32
    const float* b     = (const float*)d_in[3];  // [1] f32
    float*       out   = (float*)d_out;          // [num_segs, 256] f32

    const int N        = in_sizes[1];
    const int num_segs = out_size / CHANNELS;    // 2048

    // Zero output (harness poisons it before each timed replay)
    const int n4 = out_size / 4;
    hgp_zero_kernel<<<(n4 + THREADS - 1) / THREADS, THREADS>>>(
        (float4*)out, n4);

    // 148 SMs * 4 blocks of 8 warps = 4736 warps, ~106 nodes each
    const int blocks = 592;
    hgp_pool_kernel<<<blocks, THREADS>>>(feat, batch, W, b, out, N, num_segs);
}